// round 4
// baseline (speedup 1.0000x reference)
#include <cuda_runtime.h>

#define NN 100000
#define NE 3200000
#define H  64
#define SCAN_B 1024
#define NB ((NN + SCAN_B - 1) / SCAN_B)   // 98

// -------- device scratch (no allocations allowed) --------
__device__ int   g_cnt[NN];
__device__ int   g_row[NN + 1];
__device__ int   g_pos[NN];
__device__ float g_dis[NN];
__device__ int   g_bsum[NB];
__device__ int   g_boff[NB];
__device__ int   g_cs[NE];      // CSR: src node per slot
__device__ float g_cw[NE];      // CSR: dis[s]*dis[d] per slot
__device__ float g_tmp[NN * H]; // pre-aggregation messages (x@W)
__device__ float g_h  [NN * H]; // node features after each layer
__device__ float g_P  [NN * H]; // h2 @ Wm1[0:64]
__device__ float g_Q  [NN * H]; // h2 @ Wm1[64:128]

// -------- CSR build --------
__global__ void k_zero_cnt() {
    int i = blockIdx.x * blockDim.x + threadIdx.x;
    if (i < NN) g_cnt[i] = 0;
}

__global__ void k_hist(const int* __restrict__ dst) {
    int e = blockIdx.x * blockDim.x + threadIdx.x;
    if (e < NE) atomicAdd(&g_cnt[dst[e]], 1);
}

// ---- multi-block exclusive scan of g_cnt ----
// pass 1: per-block scan (1024 elems/block), local exclusive into g_row, block sum out
__global__ void k_scan1() {
    __shared__ int ss[SCAN_B];
    int tid = threadIdx.x;
    int i = blockIdx.x * SCAN_B + tid;
    int v = (i < NN) ? g_cnt[i] : 0;
    ss[tid] = v;
    __syncthreads();
#pragma unroll
    for (int off = 1; off < SCAN_B; off <<= 1) {
        int t = (tid >= off) ? ss[tid - off] : 0;
        __syncthreads();
        ss[tid] += t;
        __syncthreads();
    }
    if (i < NN) g_row[i] = ss[tid] - v;            // local exclusive
    if (tid == SCAN_B - 1) g_bsum[blockIdx.x] = ss[tid];
}

// pass 2: scan the NB block sums (single block)
__global__ void k_scan2() {
    __shared__ int ss[128];
    int tid = threadIdx.x;
    int v = (tid < NB) ? g_bsum[tid] : 0;
    ss[tid] = v;
    __syncthreads();
#pragma unroll
    for (int off = 1; off < 128; off <<= 1) {
        int t = (tid >= off) ? ss[tid - off] : 0;
        __syncthreads();
        ss[tid] += t;
        __syncthreads();
    }
    if (tid < NB) g_boff[tid] = ss[tid] - v;        // exclusive
}

// pass 3: add block offsets; also fuse dis = rsqrt(deg) and row[NN]
__global__ void k_scan3() {
    int i = blockIdx.x * SCAN_B + threadIdx.x;
    if (i < NN) {
        int r = g_row[i] + g_boff[blockIdx.x];
        g_row[i] = r;
        g_pos[i] = r;
        g_dis[i] = rsqrtf((float)(g_cnt[i] + 1));   // +1 self-loop
    }
    if (i == 0) g_row[NN] = NE;
}

__global__ void k_place(const int* __restrict__ src, const int* __restrict__ dst) {
    int e = blockIdx.x * blockDim.x + threadIdx.x;
    if (e >= NE) return;
    int s = src[e], d = dst[e];
    int idx = atomicAdd(&g_pos[d], 1);
    g_cs[idx] = s;
    g_cw[idx] = g_dis[s] * g_dis[d];
}

// -------- layer 1 dense: tmp = x @ W1 --------
__global__ void k_xw1(const float* __restrict__ x, const float* __restrict__ W1) {
    int t = blockIdx.x * blockDim.x + threadIdx.x;
    if (t >= NN * H) return;
    int i = t >> 6, j = t & 63;
    float4 xv = *reinterpret_cast<const float4*>(x + (size_t)i * 4);
    g_tmp[t] = xv.x * W1[j] + xv.y * W1[64 + j] + xv.z * W1[128 + j] + xv.w * W1[192 + j];
}

// -------- aggregation: g_h[n] = relu( sum_in-edges g_tmp[s]*w + g_tmp[n]*dis[n]^2 + b ) --------
// one warp per node, 2 feature columns per lane
__global__ void k_agg(const float* __restrict__ bias) {
    int w = (blockIdx.x * blockDim.x + threadIdx.x) >> 5;
    if (w >= NN) return;
    int lane = threadIdx.x & 31;
    int r = g_row[w], r1 = g_row[w + 1];
    float a0 = 0.f, a1 = 0.f;
    for (; r + 1 < r1; r += 2) {
        int   s0 = g_cs[r],     s1 = g_cs[r + 1];
        float w0 = g_cw[r],     w1 = g_cw[r + 1];
        const float* p0 = g_tmp + (size_t)s0 * H;
        const float* p1 = g_tmp + (size_t)s1 * H;
        float x00 = p0[lane], x01 = p0[lane + 32];
        float x10 = p1[lane], x11 = p1[lane + 32];
        a0 += x00 * w0; a1 += x01 * w0;
        a0 += x10 * w1; a1 += x11 * w1;
    }
    if (r < r1) {
        int s = g_cs[r]; float ww = g_cw[r];
        const float* p = g_tmp + (size_t)s * H;
        a0 += p[lane] * ww; a1 += p[lane + 32] * ww;
    }
    float dd = g_dis[w]; dd *= dd;                  // self-loop
    const float* p = g_tmp + (size_t)w * H;
    a0 += p[lane] * dd;      a1 += p[lane + 32] * dd;
    a0 += bias[lane];        a1 += bias[lane + 32];
    size_t o = (size_t)w * H;
    g_h[o + lane]      = fmaxf(a0, 0.f);
    g_h[o + lane + 32] = fmaxf(a1, 0.f);
}

// -------- layer 2 dense: tmp = h @ W2 (16 nodes / block) --------
__global__ void k_gemm2(const float* __restrict__ W2) {
    __shared__ float sW[4096];
    __shared__ float sIn[1024];
    int tid = threadIdx.x;
    int nb = blockIdx.x * 16;
    for (int i = tid; i < 4096; i += 256) sW[i] = W2[i];
    for (int i = tid; i < 1024; i += 256) sIn[i] = g_h[nb * 64 + i];
    __syncthreads();
    int col = tid & 63, ng = tid >> 6;
    float a[4] = {0.f, 0.f, 0.f, 0.f};
#pragma unroll 8
    for (int k = 0; k < 64; k++) {
        float w = sW[k * 64 + col];
#pragma unroll
        for (int m = 0; m < 4; m++) a[m] += sIn[(ng + 4 * m) * 64 + k] * w;
    }
#pragma unroll
    for (int m = 0; m < 4; m++)
        g_tmp[(size_t)(nb + ng + 4 * m) * 64 + col] = a[m];
}

// -------- P = h @ Wm1[0:64], Q = h @ Wm1[64:128] --------
__global__ void k_gemmPQ(const float* __restrict__ Wm1) {
    __shared__ float sWa[4096];
    __shared__ float sWb[4096];
    __shared__ float sIn[1024];
    int tid = threadIdx.x;
    int nb = blockIdx.x * 16;
    for (int i = tid; i < 4096; i += 256) { sWa[i] = Wm1[i]; sWb[i] = Wm1[4096 + i]; }
    for (int i = tid; i < 1024; i += 256) sIn[i] = g_h[nb * 64 + i];
    __syncthreads();
    int col = tid & 63, ng = tid >> 6;
    float p[4] = {0.f, 0.f, 0.f, 0.f};
    float q[4] = {0.f, 0.f, 0.f, 0.f};
#pragma unroll 8
    for (int k = 0; k < 64; k++) {
        float wa = sWa[k * 64 + col];
        float wb = sWb[k * 64 + col];
#pragma unroll
        for (int m = 0; m < 4; m++) {
            float xv = sIn[(ng + 4 * m) * 64 + k];
            p[m] += xv * wa;
            q[m] += xv * wb;
        }
    }
#pragma unroll
    for (int m = 0; m < 4; m++) {
        size_t o = (size_t)(nb + ng + 4 * m) * 64 + col;
        g_P[o] = p[m];
        g_Q[o] = q[m];
    }
}

// -------- edge epilogue: out[e] = relu(P[s]+Q[d]+ea@Wea+bm1) @ Wm2 + bm2 --------
// 16 lanes per edge, grid-stride; weights hoisted to registers.
__global__ void k_edge(const int* __restrict__ src, const int* __restrict__ dst,
                       const float* __restrict__ ea,
                       const float* __restrict__ Wm1, const float* __restrict__ bm1,
                       const float* __restrict__ Wm2, const float* __restrict__ bm2,
                       float* __restrict__ out) {
    int l  = threadIdx.x & 15;
    int c0 = l * 4;
    float4 w0 = *reinterpret_cast<const float4*>(Wm1 + 128 * 64 + c0);
    float4 w1 = *reinterpret_cast<const float4*>(Wm1 + 129 * 64 + c0);
    float4 w2 = *reinterpret_cast<const float4*>(Wm1 + 130 * 64 + c0);
    float4 w3 = *reinterpret_cast<const float4*>(Wm1 + 131 * 64 + c0);
    float4 bb = *reinterpret_cast<const float4*>(bm1 + c0);
    float4 wo = *reinterpret_cast<const float4*>(Wm2 + c0);
    float  ob = bm2[0];

    int grp  = (blockIdx.x * blockDim.x + threadIdx.x) >> 4;
    int ngrp = (gridDim.x * blockDim.x) >> 4;
    for (int e = grp; e < NE; e += ngrp) {
        int s = src[e], d = dst[e];
        float4 p = *reinterpret_cast<const float4*>(g_P + (size_t)s * 64 + c0);
        float4 q = *reinterpret_cast<const float4*>(g_Q + (size_t)d * 64 + c0);
        float4 a = *reinterpret_cast<const float4*>(ea + (size_t)e * 4);
        float z0 = p.x + q.x + bb.x + a.x * w0.x + a.y * w1.x + a.z * w2.x + a.w * w3.x;
        float z1 = p.y + q.y + bb.y + a.x * w0.y + a.y * w1.y + a.z * w2.y + a.w * w3.y;
        float z2 = p.z + q.z + bb.z + a.x * w0.z + a.y * w1.z + a.z * w2.z + a.w * w3.z;
        float z3 = p.w + q.w + bb.w + a.x * w0.w + a.y * w1.w + a.z * w2.w + a.w * w3.w;
        z0 = fmaxf(z0, 0.f); z1 = fmaxf(z1, 0.f); z2 = fmaxf(z2, 0.f); z3 = fmaxf(z3, 0.f);
        float part = z0 * wo.x + z1 * wo.y + z2 * wo.z + z3 * wo.w;
#pragma unroll
        for (int off = 8; off >= 1; off >>= 1)
            part += __shfl_down_sync(0xffffffffu, part, off, 16);
        if (l == 0) out[e] = part + ob;
    }
}

extern "C" void kernel_launch(void* const* d_in, const int* in_sizes, int n_in,
                              void* d_out, int out_size) {
    const float* x   = (const float*)d_in[0];
    const int*   ei  = (const int*)  d_in[1];   // [2, NE] int32
    const float* ea  = (const float*)d_in[2];
    const float* W1  = (const float*)d_in[3];
    const float* b1  = (const float*)d_in[4];
    const float* W2  = (const float*)d_in[5];
    const float* b2  = (const float*)d_in[6];
    const float* Wm1 = (const float*)d_in[7];
    const float* bm1 = (const float*)d_in[8];
    const float* Wm2 = (const float*)d_in[9];
    const float* bm2 = (const float*)d_in[10];
    float* out = (float*)d_out;

    const int* src = ei;
    const int* dst = ei + NE;

    const int TB = 256;
    int nn_blk  = (NN + TB - 1) / TB;
    int ne_blk  = (NE + TB - 1) / TB;
    int nnh_blk = (NN * H + TB - 1) / TB;
    int agg_blk = (NN + 7) / 8;                  // 8 nodes (warps) per block

    // CSR build + norm
    k_zero_cnt<<<nn_blk, TB>>>();
    k_hist<<<ne_blk, TB>>>(dst);
    k_scan1<<<NB, SCAN_B>>>();
    k_scan2<<<1, 128>>>();
    k_scan3<<<NB, SCAN_B>>>();
    k_place<<<ne_blk, TB>>>(src, dst);

    // layer 1
    k_xw1<<<nnh_blk, TB>>>(x, W1);
    k_agg<<<agg_blk, TB>>>(b1);

    // layer 2
    k_gemm2<<<NN / 16, TB>>>(W2);
    k_agg<<<agg_blk, TB>>>(b2);

    // edge MLP (factored through nodes)
    k_gemmPQ<<<NN / 16, TB>>>(Wm1);
    k_edge<<<1184, TB>>>(src, dst, ea, Wm1, bm1, Wm2, bm2, out);
}

// round 5
// speedup vs baseline: 1.5193x; 1.5193x over previous
#include <cuda_runtime.h>

#define NN 100000
#define NE 3200000
#define H  64
#define SCAN_B 1024
#define NB ((NN + SCAN_B - 1) / SCAN_B)   // 98

// -------- device scratch (no allocations allowed) --------
__device__ int   g_cnt[NN];
__device__ int   g_row[NN + 1];
__device__ int   g_pos[NN];
__device__ float g_dis[NN];
__device__ int   g_bsum[NB];
__device__ int   g_boff[NB];
__device__ int   g_cs[NE];        // CSR: src node per slot
__device__ float g_cw[NE];        // CSR: dis[s]*dis[d] per slot
__device__ float g_ax[NN * 4];    // aggregated raw x (4-dim)
__device__ float g_tmp[NN * H];   // aggregated h1 (64-dim)
__device__ float g_h  [NN * H];   // node features after each layer
__device__ float g_P  [NN * H];   // h2 @ Wm1[0:64]
__device__ float g_Q  [NN * H];   // h2 @ Wm1[64:128]

// -------- CSR build --------
__global__ void k_zero_cnt() {
    int i = blockIdx.x * blockDim.x + threadIdx.x;
    if (i < NN) g_cnt[i] = 0;
}

__global__ void k_hist(const int* __restrict__ dst) {
    int e = blockIdx.x * blockDim.x + threadIdx.x;
    if (e < NE) atomicAdd(&g_cnt[dst[e]], 1);
}

// pass 1: per-block scan (1024 elems/block), local exclusive into g_row, block sum out
__global__ void k_scan1() {
    __shared__ int ss[SCAN_B];
    int tid = threadIdx.x;
    int i = blockIdx.x * SCAN_B + tid;
    int v = (i < NN) ? g_cnt[i] : 0;
    ss[tid] = v;
    __syncthreads();
#pragma unroll
    for (int off = 1; off < SCAN_B; off <<= 1) {
        int t = (tid >= off) ? ss[tid - off] : 0;
        __syncthreads();
        ss[tid] += t;
        __syncthreads();
    }
    if (i < NN) g_row[i] = ss[tid] - v;
    if (tid == SCAN_B - 1) g_bsum[blockIdx.x] = ss[tid];
}

// pass 2: scan the NB block sums
__global__ void k_scan2() {
    __shared__ int ss[128];
    int tid = threadIdx.x;
    int v = (tid < NB) ? g_bsum[tid] : 0;
    ss[tid] = v;
    __syncthreads();
#pragma unroll
    for (int off = 1; off < 128; off <<= 1) {
        int t = (tid >= off) ? ss[tid - off] : 0;
        __syncthreads();
        ss[tid] += t;
        __syncthreads();
    }
    if (tid < NB) g_boff[tid] = ss[tid] - v;
}

// pass 3: add block offsets; fuse dis = rsqrt(deg); row[NN] = NE
__global__ void k_scan3() {
    int i = blockIdx.x * SCAN_B + threadIdx.x;
    if (i < NN) {
        int r = g_row[i] + g_boff[blockIdx.x];
        g_row[i] = r;
        g_pos[i] = r;
        g_dis[i] = rsqrtf((float)(g_cnt[i] + 1));   // +1 self-loop
    }
    if (i == 0) g_row[NN] = NE;
}

__global__ void k_place(const int* __restrict__ src, const int* __restrict__ dst) {
    int e = blockIdx.x * blockDim.x + threadIdx.x;
    if (e >= NE) return;
    int s = src[e], d = dst[e];
    int idx = atomicAdd(&g_pos[d], 1);
    g_cs[idx] = s;
    g_cw[idx] = g_dis[s] * g_dis[d];
}

// -------- layer-1 aggregation on RAW x (4-dim): ax[n] = sum w*x[s] + dis^2*x[n] --------
// one warp per node, lanes parallel over edges, float4 per edge
__global__ void k_aggx(const float* __restrict__ x) {
    int w = (blockIdx.x * blockDim.x + threadIdx.x) >> 5;
    if (w >= NN) return;
    int lane = threadIdx.x & 31;
    int r0 = g_row[w], r1 = g_row[w + 1];
    float ax = 0.f, ay = 0.f, az = 0.f, aw = 0.f;
    for (int r = r0 + lane; r < r1; r += 32) {
        int s = g_cs[r];
        float ww = g_cw[r];
        float4 xv = *reinterpret_cast<const float4*>(x + (size_t)s * 4);
        ax += xv.x * ww; ay += xv.y * ww; az += xv.z * ww; aw += xv.w * ww;
    }
#pragma unroll
    for (int off = 16; off >= 1; off >>= 1) {
        ax += __shfl_down_sync(0xffffffffu, ax, off);
        ay += __shfl_down_sync(0xffffffffu, ay, off);
        az += __shfl_down_sync(0xffffffffu, az, off);
        aw += __shfl_down_sync(0xffffffffu, aw, off);
    }
    if (lane == 0) {
        float dd = g_dis[w]; dd *= dd;
        float4 xv = *reinterpret_cast<const float4*>(x + (size_t)w * 4);
        float4 o;
        o.x = ax + dd * xv.x; o.y = ay + dd * xv.y;
        o.z = az + dd * xv.z; o.w = aw + dd * xv.w;
        *reinterpret_cast<float4*>(g_ax + (size_t)w * 4) = o;
    }
}

// -------- h1 = relu(ax @ W1 + b1) --------
__global__ void k_h1(const float* __restrict__ W1, const float* __restrict__ b1) {
    int t = blockIdx.x * blockDim.x + threadIdx.x;
    if (t >= NN * H) return;
    int i = t >> 6, j = t & 63;
    float4 a = *reinterpret_cast<const float4*>(g_ax + (size_t)i * 4);
    float s = a.x * W1[j] + a.y * W1[64 + j] + a.z * W1[128 + j] + a.w * W1[192 + j] + b1[j];
    g_h[t] = fmaxf(s, 0.f);
}

// -------- layer-2 aggregation (64-dim): tmp[n] = sum w*h1[s] + dis^2*h1[n] --------
// one warp per node, 2 feature columns per lane
__global__ void k_agg64() {
    int w = (blockIdx.x * blockDim.x + threadIdx.x) >> 5;
    if (w >= NN) return;
    int lane = threadIdx.x & 31;
    int r = g_row[w], r1 = g_row[w + 1];
    float a0 = 0.f, a1 = 0.f;
    for (; r + 1 < r1; r += 2) {
        int   s0 = g_cs[r],  s1 = g_cs[r + 1];
        float w0 = g_cw[r],  w1 = g_cw[r + 1];
        const float* p0 = g_h + (size_t)s0 * H;
        const float* p1 = g_h + (size_t)s1 * H;
        a0 += p0[lane] * w0;      a1 += p0[lane + 32] * w0;
        a0 += p1[lane] * w1;      a1 += p1[lane + 32] * w1;
    }
    if (r < r1) {
        int s = g_cs[r]; float ww = g_cw[r];
        const float* p = g_h + (size_t)s * H;
        a0 += p[lane] * ww; a1 += p[lane + 32] * ww;
    }
    float dd = g_dis[w]; dd *= dd;
    const float* p = g_h + (size_t)w * H;
    a0 += p[lane] * dd;  a1 += p[lane + 32] * dd;
    size_t o = (size_t)w * H;
    g_tmp[o + lane]      = a0;
    g_tmp[o + lane + 32] = a1;
}

// -------- h2 = relu(tmp @ W2 + b2) (16 nodes / block) --------
__global__ void k_gemm2(const float* __restrict__ W2, const float* __restrict__ b2) {
    __shared__ float sW[4096];
    __shared__ float sIn[1024];
    int tid = threadIdx.x;
    int nb = blockIdx.x * 16;
    for (int i = tid; i < 4096; i += 256) sW[i] = W2[i];
    for (int i = tid; i < 1024; i += 256) sIn[i] = g_tmp[nb * 64 + i];
    __syncthreads();
    int col = tid & 63, ng = tid >> 6;
    float a[4] = {0.f, 0.f, 0.f, 0.f};
#pragma unroll 8
    for (int k = 0; k < 64; k++) {
        float w = sW[k * 64 + col];
#pragma unroll
        for (int m = 0; m < 4; m++) a[m] += sIn[(ng + 4 * m) * 64 + k] * w;
    }
    float bb = b2[col];
#pragma unroll
    for (int m = 0; m < 4; m++)
        g_h[(size_t)(nb + ng + 4 * m) * 64 + col] = fmaxf(a[m] + bb, 0.f);
}

// -------- P = h2 @ Wm1[0:64], Q = h2 @ Wm1[64:128] --------
__global__ void k_gemmPQ(const float* __restrict__ Wm1) {
    __shared__ float sWa[4096];
    __shared__ float sWb[4096];
    __shared__ float sIn[1024];
    int tid = threadIdx.x;
    int nb = blockIdx.x * 16;
    for (int i = tid; i < 4096; i += 256) { sWa[i] = Wm1[i]; sWb[i] = Wm1[4096 + i]; }
    for (int i = tid; i < 1024; i += 256) sIn[i] = g_h[nb * 64 + i];
    __syncthreads();
    int col = tid & 63, ng = tid >> 6;
    float p[4] = {0.f, 0.f, 0.f, 0.f};
    float q[4] = {0.f, 0.f, 0.f, 0.f};
#pragma unroll 8
    for (int k = 0; k < 64; k++) {
        float wa = sWa[k * 64 + col];
        float wb = sWb[k * 64 + col];
#pragma unroll
        for (int m = 0; m < 4; m++) {
            float xv = sIn[(ng + 4 * m) * 64 + k];
            p[m] += xv * wa;
            q[m] += xv * wb;
        }
    }
#pragma unroll
    for (int m = 0; m < 4; m++) {
        size_t o = (size_t)(nb + ng + 4 * m) * 64 + col;
        g_P[o] = p[m];
        g_Q[o] = q[m];
    }
}

// -------- edge epilogue: out[e] = relu(P[s]+Q[d]+ea@Wea+bm1) @ Wm2 + bm2 --------
__global__ void k_edge(const int* __restrict__ src, const int* __restrict__ dst,
                       const float* __restrict__ ea,
                       const float* __restrict__ Wm1, const float* __restrict__ bm1,
                       const float* __restrict__ Wm2, const float* __restrict__ bm2,
                       float* __restrict__ out) {
    int l  = threadIdx.x & 15;
    int c0 = l * 4;
    float4 w0 = *reinterpret_cast<const float4*>(Wm1 + 128 * 64 + c0);
    float4 w1 = *reinterpret_cast<const float4*>(Wm1 + 129 * 64 + c0);
    float4 w2 = *reinterpret_cast<const float4*>(Wm1 + 130 * 64 + c0);
    float4 w3 = *reinterpret_cast<const float4*>(Wm1 + 131 * 64 + c0);
    float4 bb = *reinterpret_cast<const float4*>(bm1 + c0);
    float4 wo = *reinterpret_cast<const float4*>(Wm2 + c0);
    float  ob = bm2[0];

    int grp  = (blockIdx.x * blockDim.x + threadIdx.x) >> 4;
    int ngrp = (gridDim.x * blockDim.x) >> 4;
    for (int e = grp; e < NE; e += ngrp) {
        int s = src[e], d = dst[e];
        float4 p = *reinterpret_cast<const float4*>(g_P + (size_t)s * 64 + c0);
        float4 q = *reinterpret_cast<const float4*>(g_Q + (size_t)d * 64 + c0);
        float4 a = *reinterpret_cast<const float4*>(ea + (size_t)e * 4);
        float z0 = p.x + q.x + bb.x + a.x * w0.x + a.y * w1.x + a.z * w2.x + a.w * w3.x;
        float z1 = p.y + q.y + bb.y + a.x * w0.y + a.y * w1.y + a.z * w2.y + a.w * w3.y;
        float z2 = p.z + q.z + bb.z + a.x * w0.z + a.y * w1.z + a.z * w2.z + a.w * w3.z;
        float z3 = p.w + q.w + bb.w + a.x * w0.w + a.y * w1.w + a.z * w2.w + a.w * w3.w;
        z0 = fmaxf(z0, 0.f); z1 = fmaxf(z1, 0.f); z2 = fmaxf(z2, 0.f); z3 = fmaxf(z3, 0.f);
        float part = z0 * wo.x + z1 * wo.y + z2 * wo.z + z3 * wo.w;
#pragma unroll
        for (int off = 8; off >= 1; off >>= 1)
            part += __shfl_down_sync(0xffffffffu, part, off, 16);
        if (l == 0) out[e] = part + ob;
    }
}

extern "C" void kernel_launch(void* const* d_in, const int* in_sizes, int n_in,
                              void* d_out, int out_size) {
    const float* x   = (const float*)d_in[0];
    const int*   ei  = (const int*)  d_in[1];   // [2, NE] int32
    const float* ea  = (const float*)d_in[2];
    const float* W1  = (const float*)d_in[3];
    const float* b1  = (const float*)d_in[4];
    const float* W2  = (const float*)d_in[5];
    const float* b2  = (const float*)d_in[6];
    const float* Wm1 = (const float*)d_in[7];
    const float* bm1 = (const float*)d_in[8];
    const float* Wm2 = (const float*)d_in[9];
    const float* bm2 = (const float*)d_in[10];
    float* out = (float*)d_out;

    const int* src = ei;
    const int* dst = ei + NE;

    const int TB = 256;
    int nn_blk  = (NN + TB - 1) / TB;
    int ne_blk  = (NE + TB - 1) / TB;
    int nnh_blk = (NN * H + TB - 1) / TB;
    int agg_blk = (NN + 7) / 8;                  // 8 warps (nodes) per block

    // CSR build + norm
    k_zero_cnt<<<nn_blk, TB>>>();
    k_hist<<<ne_blk, TB>>>(dst);
    k_scan1<<<NB, SCAN_B>>>();
    k_scan2<<<1, 128>>>();
    k_scan3<<<NB, SCAN_B>>>();
    k_place<<<ne_blk, TB>>>(src, dst);

    // layer 1: aggregate raw x (4-dim), then dense W1+bias+relu
    k_aggx<<<agg_blk, TB>>>(x);
    k_h1<<<nnh_blk, TB>>>(W1, b1);

    // layer 2: aggregate h1 (64-dim), then dense W2+bias+relu
    k_agg64<<<agg_blk, TB>>>();
    k_gemm2<<<NN / 16, TB>>>(W2, b2);

    // edge MLP (factored through nodes)
    k_gemmPQ<<<NN / 16, TB>>>(Wm1);
    k_edge<<<1184, TB>>>(src, dst, ea, Wm1, bm1, Wm2, bm2, out);
}